// round 11
// baseline (speedup 1.0000x reference)
#include <cuda_runtime.h>
#include <cuda_bf16.h>
#include <cstdint>

// Problem constants (fixed by setup_inputs): T=128, N=2048, D=256, w=3
#define T_SNAP 128
#define N_NODE 2048
#define D_HID  256
#define WIN    3
#define ROWS   (T_SNAP * N_NODE)   // 262144

// Scratch (allocation-free rule: __device__ globals)
__device__ float g_score[ROWS];
__device__ float g_p[ROWS];
// Pre-packed W: g_Wb[(c*16 + k2)*256 + n] = bf16x2{ W[32c+2k2][n], W[32c+2k2+1][n] }
__device__ uint32_t g_Wb[8 * 16 * 256];   // 128 KB

// ---------------------------------------------------------------------------
__device__ __forceinline__ uint32_t pack_bf16(float lo, float hi) {
    __nv_bfloat162 h = __floats2bfloat162_rn(lo, hi);
    return *reinterpret_cast<uint32_t*>(&h);
}

__device__ __forceinline__ void mma_bf16(float* c, const uint32_t* a, const uint32_t* b) {
    asm volatile(
        "mma.sync.aligned.m16n8k16.row.col.f32.bf16.bf16.f32 "
        "{%0,%1,%2,%3}, {%4,%5,%6,%7}, {%8,%9}, {%0,%1,%2,%3};"
        : "+f"(c[0]), "+f"(c[1]), "+f"(c[2]), "+f"(c[3])
        : "r"(a[0]), "r"(a[1]), "r"(a[2]), "r"(a[3]), "r"(b[0]), "r"(b[1]));
}

__device__ __forceinline__ void cp_async16(uint32_t smem_dst, const void* gptr) {
    asm volatile("cp.async.cg.shared.global [%0], [%1], 16;"
                 :: "r"(smem_dst), "l"(gptr) : "memory");
}
__device__ __forceinline__ void cp_commit() {
    asm volatile("cp.async.commit_group;" ::: "memory");
}
__device__ __forceinline__ void cp_wait_all() {
    asm volatile("cp.async.wait_group 0;" ::: "memory");
}

// ---------------------------------------------------------------------------
// Kernel 0: pack W into bf16x2 chunk layout (one-shot, ~µs)
// ---------------------------------------------------------------------------
__global__ __launch_bounds__(256) void prep_w_kernel(const float* __restrict__ W)
{
    int idx = blockIdx.x * 256 + threadIdx.x;  // 0..32767
    int n  = idx & 255;
    int kk = idx >> 8;                         // global k-pair 0..127
    g_Wb[idx] = pack_bf16(W[(2 * kk) * D_HID + n], W[(2 * kk + 1) * D_HID + n]);
}

// ---------------------------------------------------------------------------
// Kernel 1 (mma.sync bf16, pipelined — best measured config, FROZEN):
//   score[row] = proj . tanh( X[row,:] @ W )
// ---------------------------------------------------------------------------
#define AS_STRIDE 20    // u32: banks (20*qid+qlane)%32 all distinct
#define BS_STRIDE 264   // u32: banks (8*qlane+qid)%32 all distinct

__global__ __launch_bounds__(256, 2) void score_kernel(
    const float4* __restrict__ X4,
    const float*  __restrict__ proj)
{
    __shared__ uint32_t As[2][64 * AS_STRIDE];   // 10 KB
    __shared__ uint32_t Bs[2][16 * BS_STRIDE];   // 33.8 KB
    __shared__ float sproj[D_HID];
    __shared__ float part[4][64];

    const int tid    = threadIdx.x;
    const int lane   = tid & 31;
    const int wid    = tid >> 5;
    const int warp_m = wid >> 2;
    const int warp_n = wid & 3;
    const int qid    = lane >> 2;
    const int qlane  = lane & 3;
    const int row0   = blockIdx.x * 64;

    sproj[tid] = proj[tid];

    const int am0 = tid >> 3,         ac0 = tid & 7;
    const int am1 = (tid + 256) >> 3, ac1 = (tid + 256) & 7;
    const uint32_t bs_base = (uint32_t)__cvta_generic_to_shared(&Bs[0][0]);

    float acc[2][8][4];
    #pragma unroll
    for (int mt = 0; mt < 2; mt++)
        #pragma unroll
        for (int nt = 0; nt < 8; nt++)
            #pragma unroll
            for (int i = 0; i < 4; i++) acc[mt][nt][i] = 0.0f;

    auto stageB = [&](int c, int bf) {
        #pragma unroll
        for (int i = 0; i < 4; i++) {
            int seg = tid + i * 256;             // 0..1023
            int k2  = seg >> 6;
            int ng  = seg & 63;
            cp_async16(bs_base + (bf * 16 * BS_STRIDE + k2 * BS_STRIDE + ng * 4) * 4,
                       &g_Wb[(c * 16 + k2) * 256 + ng * 4]);
        }
    };
    auto stsA = [&](int bf, float4 v0, float4 v1) {
        uint2 u;
        u.x = pack_bf16(v0.x, v0.y); u.y = pack_bf16(v0.z, v0.w);
        *reinterpret_cast<uint2*>(&As[bf][am0 * AS_STRIDE + ac0 * 2]) = u;
        u.x = pack_bf16(v1.x, v1.y); u.y = pack_bf16(v1.z, v1.w);
        *reinterpret_cast<uint2*>(&As[bf][am1 * AS_STRIDE + ac1 * 2]) = u;
    };

    // ---- Prologue: stage chunk 0 ----
    float4 pa0 = X4[(row0 + am0) * 64 + ac0];
    float4 pa1 = X4[(row0 + am1) * 64 + ac1];
    stageB(0, 0); cp_commit();
    stsA(0, pa0, pa1);
    cp_wait_all();
    __syncthreads();

    #pragma unroll 1
    for (int c = 0; c < 8; ++c) {
        const int buf = c & 1;
        const int nxt = buf ^ 1;

        if (c < 7) {
            pa0 = X4[(row0 + am0) * 64 + (c + 1) * 8 + ac0];
            pa1 = X4[(row0 + am1) * 64 + (c + 1) * 8 + ac1];
            stageB(c + 1, nxt); cp_commit();
        }

        #pragma unroll
        for (int ks = 0; ks < 2; ks++) {
            const int k2b = ks * 8;
            uint32_t a[2][4];
            #pragma unroll
            for (int mt = 0; mt < 2; mt++) {
                int r = warp_m * 32 + mt * 16 + qid;
                a[mt][0] = As[buf][r * AS_STRIDE + k2b + qlane];
                a[mt][1] = As[buf][(r + 8) * AS_STRIDE + k2b + qlane];
                a[mt][2] = As[buf][r * AS_STRIDE + k2b + qlane + 4];
                a[mt][3] = As[buf][(r + 8) * AS_STRIDE + k2b + qlane + 4];
            }
            uint32_t b[8][2];
            #pragma unroll
            for (int nt = 0; nt < 8; nt++) {
                int n = warp_n * 64 + nt * 8 + qid;
                b[nt][0] = Bs[buf][(k2b + qlane)     * BS_STRIDE + n];
                b[nt][1] = Bs[buf][(k2b + qlane + 4) * BS_STRIDE + n];
            }
            #pragma unroll
            for (int mt = 0; mt < 2; mt++)
                #pragma unroll
                for (int nt = 0; nt < 8; nt++)
                    mma_bf16(acc[mt][nt], a[mt], b[nt]);
        }

        if (c < 7) {
            stsA(nxt, pa0, pa1);
            cp_wait_all();
            __syncthreads();
        }
    }

    // Fused epilogue
    float psum[2][2];
    psum[0][0] = psum[0][1] = psum[1][0] = psum[1][1] = 0.0f;
    #pragma unroll
    for (int mt = 0; mt < 2; mt++)
        #pragma unroll
        for (int nt = 0; nt < 8; nt++) {
            int cb = warp_n * 64 + nt * 8 + 2 * qlane;
            float p0 = sproj[cb], p1 = sproj[cb + 1];
            psum[mt][0] += tanhf(acc[mt][nt][0]) * p0 + tanhf(acc[mt][nt][1]) * p1;
            psum[mt][1] += tanhf(acc[mt][nt][2]) * p0 + tanhf(acc[mt][nt][3]) * p1;
        }
    #pragma unroll
    for (int off = 1; off < 4; off <<= 1) {
        #pragma unroll
        for (int mt = 0; mt < 2; mt++) {
            psum[mt][0] += __shfl_xor_sync(0xffffffffu, psum[mt][0], off);
            psum[mt][1] += __shfl_xor_sync(0xffffffffu, psum[mt][1], off);
        }
    }
    __syncthreads();
    if (qlane == 0) {
        #pragma unroll
        for (int mt = 0; mt < 2; mt++) {
            part[warp_n][warp_m * 32 + mt * 16 + qid]     = psum[mt][0];
            part[warp_n][warp_m * 32 + mt * 16 + qid + 8] = psum[mt][1];
        }
    }
    __syncthreads();
    if (tid < 64)
        g_score[row0 + tid] =
            part[0][tid] + part[1][tid] + part[2][tid] + part[3][tid];
}

// ---------------------------------------------------------------------------
// Kernel 2: p[j,:] = softmax over N of score[j,:]   (one block per row j)
// ---------------------------------------------------------------------------
__global__ __launch_bounds__(256) void softmax_kernel()
{
    __shared__ float red_max[8];
    __shared__ float red_sum[8];
    const int j   = blockIdx.x;
    const int tid = threadIdx.x;
    const float* row = g_score + j * N_NODE;

    float v[8];
    float m = -1e30f;
    #pragma unroll
    for (int i = 0; i < 8; i++) {
        v[i] = row[tid + i * 256];
        m = fmaxf(m, v[i]);
    }
    #pragma unroll
    for (int off = 16; off > 0; off >>= 1)
        m = fmaxf(m, __shfl_xor_sync(0xffffffffu, m, off));
    if ((tid & 31) == 0) red_max[tid >> 5] = m;
    __syncthreads();
    float bm = red_max[0];
    #pragma unroll
    for (int wq = 1; wq < 8; wq++) bm = fmaxf(bm, red_max[wq]);

    float s = 0.0f;
    #pragma unroll
    for (int i = 0; i < 8; i++) {
        v[i] = expf(v[i] - bm);
        s += v[i];
    }
    #pragma unroll
    for (int off = 16; off > 0; off >>= 1)
        s += __shfl_xor_sync(0xffffffffu, s, off);
    if ((tid & 31) == 0) red_sum[tid >> 5] = s;
    __syncthreads();
    float bs = 0.0f;
    #pragma unroll
    for (int wq = 0; wq < 8; wq++) bs += red_sum[wq];
    float inv = 1.0f / bs;

    #pragma unroll
    for (int i = 0; i < 8; i++)
        g_p[j * N_NODE + tid + i * 256] = v[i] * inv;
}

// ---------------------------------------------------------------------------
// Kernel 3: out, temporal-reuse version. Each thread owns a fixed (n, dp)
// column and marches a 32-snapshot strip with rolling 3-deep register windows
// of X (float4) and p (scalar). X is read from DRAM exactly once (+3 prime
// loads per strip); p loads are warp-broadcast L2 hits.
// Grid: 4 strips x 512 n-blocks; block = 4 n x 64 dp.
// ---------------------------------------------------------------------------
#define TSTRIP 32

__global__ __launch_bounds__(256) void out_kernel(
    const float4* __restrict__ X4,
    float4* __restrict__ out4)
{
    const int ts = blockIdx.x >> 9;                       // strip 0..3
    const int nb = blockIdx.x & 511;
    const int n  = nb * 4 + (threadIdx.x >> 6);           // node
    const int dp = threadIdx.x & 63;                      // float4 within D

    const int istart = ts * TSTRIP;
    const int ibegin = (ts == 0) ? 0 : istart - WIN;

    float4 w0 = {0,0,0,0}, w1 = {0,0,0,0}, w2 = {0,0,0,0};
    float  q0 = 0.0f, q1 = 0.0f, q2 = 0.0f;

    for (int i = ibegin; i < istart + TSTRIP; ++i) {
        const int ridx = i * N_NODE + n;
        float4 xi = X4[ridx * 64 + dp];
        float  pi = g_p[ridx];

        if (i >= istart) {
            float4 o;
            if (i < WIN) {
                o = xi;
            } else {
                o.x = q0 * w0.x + q1 * w1.x + q2 * w2.x;
                o.y = q0 * w0.y + q1 * w1.y + q2 * w2.y;
                o.z = q0 * w0.z + q1 * w1.z + q2 * w2.z;
                o.w = q0 * w0.w + q1 * w1.w + q2 * w2.w;
            }
            out4[ridx * 64 + dp] = o;
        }
        w0 = w1; w1 = w2; w2 = xi;
        q0 = q1; q1 = q2; q2 = pi;
    }
}

// ---------------------------------------------------------------------------
extern "C" void kernel_launch(void* const* d_in, const int* in_sizes, int n_in,
                              void* d_out, int out_size)
{
    const float* X    = (const float*)d_in[0];  // (128, 2048, 256)
    const float* W    = (const float*)d_in[1];  // (256, 256)
    const float* proj = (const float*)d_in[2];  // (256, 1)
    float* out        = (float*)d_out;

    prep_w_kernel<<<128, 256>>>(W);
    score_kernel<<<ROWS / 64, 256>>>((const float4*)X, proj);
    softmax_kernel<<<T_SNAP, 256>>>();
    out_kernel<<<(T_SNAP / TSTRIP) * 512, 256>>>((const float4*)X, (float4*)out);
}